// round 2
// baseline (speedup 1.0000x reference)
#include <cuda_runtime.h>
#include <cstdint>
#include <cstring>

#define Nn 8192
#define FIN 512
#define FOUT 64
#define GAT_ALPHA 0.2f

// ---------------- scratch (device globals: no allocation allowed) ----------------
__device__ float g_h[Nn * FOUT];
__device__ float g_ssrc[Nn];
__device__ float g_sdst[Nn];
__device__ float g_part[1024];
__device__ float g_gmax;

// ---------------- helpers ----------------
__device__ __forceinline__ float lrelu(float x) { return x > 0.f ? x : GAT_ALPHA * x; }

__device__ __forceinline__ unsigned long long pack2(float x, float y) {
    unsigned long long r;
    asm("mov.b64 %0, {%1, %2};" : "=l"(r) : "f"(x), "f"(y));
    return r;
}
__device__ __forceinline__ float2 unpack2(unsigned long long v) {
    float2 f;
    asm("mov.b64 {%0, %1}, %2;" : "=f"(f.x), "=f"(f.y) : "l"(v));
    return f;
}
// Blackwell packed fp32 FMA: 2 MACs per instruction on the FMA pipe.
__device__ __forceinline__ unsigned long long ffma2(unsigned long long a,
                                                    unsigned long long b,
                                                    unsigned long long c) {
    unsigned long long d;
    asm("fma.rn.f32x2 %0, %1, %2, %3;" : "=l"(d) : "l"(a), "l"(b), "l"(c));
    return d;
}

// ---------------- kernel 1: h = input @ W ----------------
// 512 blocks x 256 threads, 16 rows per block. Input tile staged in SMEM (32KB),
// W streamed through L1 (reused by 4 row-groups in flight).
__global__ __launch_bounds__(256) void k_proj(const float* __restrict__ input,
                                              const float* __restrict__ Wm) {
    __shared__ float in_s[16 * 512];
    const int t = threadIdx.x;
    const int i0 = blockIdx.x * 16;

#pragma unroll
    for (int q = 0; q < 8; ++q) {
        int idx = q * 256 + t;          // float4 units: 16*512/4 = 2048
        int row = idx >> 7;             // 128 float4 per row
        int c4 = idx & 127;
        *(float4*)(in_s + row * 512 + c4 * 4) =
            *(const float4*)(input + (size_t)(i0 + row) * 512 + c4 * 4);
    }
    __syncthreads();

    const int f = t & 63;
    const int rg = t >> 6;              // 0..3, 4 rows each
    float acc[4] = {0.f, 0.f, 0.f, 0.f};
    const float* ip = in_s + rg * 4 * 512;

    for (int k = 0; k < 512; k += 4) {
        float w0 = __ldg(Wm + (k + 0) * 64 + f);
        float w1 = __ldg(Wm + (k + 1) * 64 + f);
        float w2 = __ldg(Wm + (k + 2) * 64 + f);
        float w3 = __ldg(Wm + (k + 3) * 64 + f);
#pragma unroll
        for (int i = 0; i < 4; ++i) {
            float4 iv = *(const float4*)(ip + i * 512 + k);
            acc[i] = fmaf(iv.x, w0, acc[i]);
            acc[i] = fmaf(iv.y, w1, acc[i]);
            acc[i] = fmaf(iv.z, w2, acc[i]);
            acc[i] = fmaf(iv.w, w3, acc[i]);
        }
    }
#pragma unroll
    for (int i = 0; i < 4; ++i)
        g_h[(size_t)(i0 + rg * 4 + i) * 64 + f] = acc[i];
}

// ---------------- kernel 1b: s_src, s_dst, per-block max(s_dst) ----------------
// 1024 blocks x 256 threads, one warp per row.
__global__ __launch_bounds__(256) void k_scores(const float* __restrict__ av) {
    __shared__ float sdm[8];
    const int t = threadIdx.x;
    const int w = t >> 5, l = t & 31;
    const int row = blockIdx.x * 8 + w;

    float v0 = g_h[(size_t)row * 64 + l];
    float v1 = g_h[(size_t)row * 64 + 32 + l];
    float ss = v0 * __ldg(av + l) + v1 * __ldg(av + 32 + l);
    float sd = v0 * __ldg(av + 64 + l) + v1 * __ldg(av + 96 + l);
#pragma unroll
    for (int o = 16; o; o >>= 1) {
        ss += __shfl_xor_sync(0xffffffffu, ss, o);
        sd += __shfl_xor_sync(0xffffffffu, sd, o);
    }
    if (l == 0) {
        g_ssrc[row] = ss;
        g_sdst[row] = sd;
        sdm[w] = sd;
    }
    __syncthreads();
    if (t == 0) {
        float m = sdm[0];
#pragma unroll
        for (int i = 1; i < 8; ++i) m = fmaxf(m, sdm[i]);
        g_part[blockIdx.x] = m;
    }
}

// ---------------- kernel 1c: global max(s_dst) ----------------
__global__ __launch_bounds__(1024) void k_max() {
    __shared__ float s[1024];
    const int t = threadIdx.x;
    s[t] = g_part[t];
    __syncthreads();
    for (int o = 512; o; o >>= 1) {
        if (t < o) s[t] = fmaxf(s[t], s[t + o]);
        __syncthreads();
    }
    if (t == 0) g_gmax = s[0];
}

// ---------------- kernel 2: masked softmax attention + att @ h ----------------
// 128 blocks x 256 threads. Block owns 64 rows; j streamed in 64-chunks.
// Register double-buffer on adj/h hides DRAM latency behind the FMA phase.
// GEMM phase: 16(fg) x 16(rg) threads, 4 rows x 4 feats micro-tile, FFMA2.
__global__ __launch_bounds__(256) void k_attn(const int* __restrict__ adj,
                                              float* __restrict__ out) {
    __shared__ float h_s[64 * 64];          // h tile, [jj][f]
    __shared__ float p_t[64 * 66];          // p transposed, [jj][r], pad 66
    __shared__ float ssrc_s[64], m_s[64], zrow_s[64];

    const int t = threadIdx.x;
    const int i0 = blockIdx.x * 64;
    const int fg = t & 15;                  // feature group (4 feats) / adj col group
    const int rg = t >> 4;                  // row group (4 rows) / staging row-in-16

    if (t < 64) {
        float s = g_ssrc[i0 + t];
        ssrc_s[t] = s;
        m_s[t] = lrelu(s + g_gmax);         // per-row softmax upper bound
        zrow_s[t] = 0.f;
    }

    unsigned long long acc[4][2];
#pragma unroll
    for (int i = 0; i < 4; ++i) { acc[i][0] = 0ULL; acc[i][1] = 0ULL; }
    float zacc[4] = {0.f, 0.f, 0.f, 0.f};

    int4 abuf[4];
    float4 hbuf[4];
    // prologue: prefetch chunk 0
#pragma unroll
    for (int q = 0; q < 4; ++q) {
        int r = q * 16 + rg;
        abuf[q] = *(const int4*)(adj + (size_t)(i0 + r) * Nn + fg * 4);
        hbuf[q] = *(const float4*)(g_h + (size_t)r * 64 + fg * 4);
    }

    for (int c = 0; c < 128; ++c) {
        const int j0 = c * 64;
        __syncthreads();                    // previous GEMM phase done with tiles

        // stage h tile + compute p tile from registers
#pragma unroll
        for (int q = 0; q < 4; ++q) {
            int r = q * 16 + rg;
            *(float4*)(h_s + r * 64 + fg * 4) = hbuf[q];
            float srow = ssrc_s[r];
            float mrow = m_s[r];
            int jj = fg * 4;
            int av0 = abuf[q].x, av1 = abuf[q].y, av2 = abuf[q].z, av3 = abuf[q].w;
            float z = 0.f;
            {
                float sd = __ldg(g_sdst + j0 + jj + 0);
                float p = (av0 > 0) ? __expf(lrelu(srow + sd) - mrow) : 0.f;
                z += p; p_t[(jj + 0) * 66 + r] = p;
            }
            {
                float sd = __ldg(g_sdst + j0 + jj + 1);
                float p = (av1 > 0) ? __expf(lrelu(srow + sd) - mrow) : 0.f;
                z += p; p_t[(jj + 1) * 66 + r] = p;
            }
            {
                float sd = __ldg(g_sdst + j0 + jj + 2);
                float p = (av2 > 0) ? __expf(lrelu(srow + sd) - mrow) : 0.f;
                z += p; p_t[(jj + 2) * 66 + r] = p;
            }
            {
                float sd = __ldg(g_sdst + j0 + jj + 3);
                float p = (av3 > 0) ? __expf(lrelu(srow + sd) - mrow) : 0.f;
                z += p; p_t[(jj + 3) * 66 + r] = p;
            }
            zacc[q] += z;
        }
        __syncthreads();

        // prefetch next chunk (overlaps with GEMM phase below)
        if (c < 127) {
            const int j1 = j0 + 64;
#pragma unroll
            for (int q = 0; q < 4; ++q) {
                int r = q * 16 + rg;
                abuf[q] = *(const int4*)(adj + (size_t)(i0 + r) * Nn + j1 + fg * 4);
                hbuf[q] = *(const float4*)(g_h + (size_t)(j1 + r) * 64 + fg * 4);
            }
        }

        // GEMM phase: out[4 rows][4 feats] += p * h   (FFMA2, 8 per jj per thread)
#pragma unroll 8
        for (int jj = 0; jj < 64; ++jj) {
            const float* hp = h_s + jj * 64 + fg * 4;
            unsigned long long hv0 = *(const unsigned long long*)(hp);
            unsigned long long hv1 = *(const unsigned long long*)(hp + 2);
            const float* pp = p_t + jj * 66 + rg * 4;
            float2 pa = *(const float2*)(pp);
            float2 pb = *(const float2*)(pp + 2);
            unsigned long long p0 = pack2(pa.x, pa.x);
            unsigned long long p1 = pack2(pa.y, pa.y);
            unsigned long long p2 = pack2(pb.x, pb.x);
            unsigned long long p3 = pack2(pb.y, pb.y);
            acc[0][0] = ffma2(p0, hv0, acc[0][0]);
            acc[0][1] = ffma2(p0, hv1, acc[0][1]);
            acc[1][0] = ffma2(p1, hv0, acc[1][0]);
            acc[1][1] = ffma2(p1, hv1, acc[1][1]);
            acc[2][0] = ffma2(p2, hv0, acc[2][0]);
            acc[2][1] = ffma2(p2, hv1, acc[2][1]);
            acc[3][0] = ffma2(p3, hv0, acc[3][0]);
            acc[3][1] = ffma2(p3, hv1, acc[3][1]);
        }
    }

    __syncthreads();
#pragma unroll
    for (int q = 0; q < 4; ++q)
        atomicAdd(&zrow_s[q * 16 + rg], zacc[q]);
    __syncthreads();

#pragma unroll
    for (int i = 0; i < 4; ++i) {
        int r = rg * 4 + i;
        float zinv = 1.0f / zrow_s[r];
        float2 a0 = unpack2(acc[i][0]);
        float2 a1 = unpack2(acc[i][1]);
        float4 o;
        o.x = a0.x * zinv; o.y = a0.y * zinv;
        o.z = a1.x * zinv; o.w = a1.y * zinv;
        *(float4*)(out + (size_t)(i0 + r) * 64 + fg * 4) = o;
    }
}

// ---------------- launch ----------------
extern "C" void kernel_launch(void* const* d_in, const int* in_sizes, int n_in,
                              void* d_out, int out_size) {
    const float* input = (const float*)d_in[0];   // [8192, 512] f32
    const int*   adj   = (const int*)d_in[1];     // [8192, 8192] i32
    const float* Wm    = (const float*)d_in[2];   // [512, 64] f32
    const float* av    = (const float*)d_in[3];   // [128, 1] f32
    float* out = (float*)d_out;                   // [8192, 64] f32

    k_proj<<<Nn / 16, 256>>>(input, Wm);
    k_scores<<<Nn / 8, 256>>>(av);
    k_max<<<1, 1024>>>();
    k_attn<<<Nn / 64, 256>>>(adj, out);
}

// round 3
// speedup vs baseline: 1.5697x; 1.5697x over previous
#include <cuda_runtime.h>
#include <cstdint>

#define Nn 8192
#define FOUT 64
#define GAT_ALPHA 0.2f
#define LOG2E 1.4426950408889634f

// ---------------- scratch ----------------
__device__ float g_h[Nn * FOUT];
__device__ float g_ssrc[Nn];
__device__ float g_sdst[Nn];
__device__ float g_part[1024];
__device__ float g_gmax;
__device__ float g_o4[4 * Nn * FOUT];   // partial (unnormalized) outputs per j-quarter
__device__ float g_z4[4 * Nn];          // partial softmax denominators

// ---------------- helpers ----------------
__device__ __forceinline__ float lrelu(float x) { return fmaxf(x, GAT_ALPHA * x); }

__device__ __forceinline__ unsigned long long pack2(float x, float y) {
    unsigned long long r;
    asm("mov.b64 %0, {%1, %2};" : "=l"(r) : "f"(x), "f"(y));
    return r;
}
__device__ __forceinline__ float2 unpack2(unsigned long long v) {
    float2 f;
    asm("mov.b64 {%0, %1}, %2;" : "=f"(f.x), "=f"(f.y) : "l"(v));
    return f;
}
__device__ __forceinline__ unsigned long long ffma2(unsigned long long a,
                                                    unsigned long long b,
                                                    unsigned long long c) {
    unsigned long long d;
    asm("fma.rn.f32x2 %0, %1, %2, %3;" : "=l"(d) : "l"(a), "l"(b), "l"(c));
    return d;
}

// ---------------- kernel 1: h = input @ W ----------------
__global__ __launch_bounds__(256) void k_proj(const float* __restrict__ input,
                                              const float* __restrict__ Wm) {
    __shared__ float in_s[16 * 512];
    const int t = threadIdx.x;
    const int i0 = blockIdx.x * 16;
#pragma unroll
    for (int q = 0; q < 8; ++q) {
        int idx = q * 256 + t;
        int row = idx >> 7;
        int c4 = idx & 127;
        *(float4*)(in_s + row * 512 + c4 * 4) =
            *(const float4*)(input + (size_t)(i0 + row) * 512 + c4 * 4);
    }
    __syncthreads();
    const int f = t & 63;
    const int rg = t >> 6;
    float acc[4] = {0.f, 0.f, 0.f, 0.f};
    const float* ip = in_s + rg * 4 * 512;
    for (int k = 0; k < 512; k += 4) {
        float w0 = __ldg(Wm + (k + 0) * 64 + f);
        float w1 = __ldg(Wm + (k + 1) * 64 + f);
        float w2 = __ldg(Wm + (k + 2) * 64 + f);
        float w3 = __ldg(Wm + (k + 3) * 64 + f);
#pragma unroll
        for (int i = 0; i < 4; ++i) {
            float4 iv = *(const float4*)(ip + i * 512 + k);
            acc[i] = fmaf(iv.x, w0, acc[i]);
            acc[i] = fmaf(iv.y, w1, acc[i]);
            acc[i] = fmaf(iv.z, w2, acc[i]);
            acc[i] = fmaf(iv.w, w3, acc[i]);
        }
    }
#pragma unroll
    for (int i = 0; i < 4; ++i)
        g_h[(size_t)(i0 + rg * 4 + i) * 64 + f] = acc[i];
}

// ---------------- kernel 1b: s_src, s_dst, partial max ----------------
__global__ __launch_bounds__(256) void k_scores(const float* __restrict__ av) {
    __shared__ float sdm[8];
    const int t = threadIdx.x;
    const int w = t >> 5, l = t & 31;
    const int row = blockIdx.x * 8 + w;
    float v0 = g_h[(size_t)row * 64 + l];
    float v1 = g_h[(size_t)row * 64 + 32 + l];
    float ss = v0 * __ldg(av + l) + v1 * __ldg(av + 32 + l);
    float sd = v0 * __ldg(av + 64 + l) + v1 * __ldg(av + 96 + l);
#pragma unroll
    for (int o = 16; o; o >>= 1) {
        ss += __shfl_xor_sync(0xffffffffu, ss, o);
        sd += __shfl_xor_sync(0xffffffffu, sd, o);
    }
    if (l == 0) {
        g_ssrc[row] = ss;
        g_sdst[row] = sd;
        sdm[w] = sd;
    }
    __syncthreads();
    if (t == 0) {
        float m = sdm[0];
#pragma unroll
        for (int i = 1; i < 8; ++i) m = fmaxf(m, sdm[i]);
        g_part[blockIdx.x] = m;
    }
}

__global__ __launch_bounds__(1024) void k_max() {
    __shared__ float s[1024];
    const int t = threadIdx.x;
    s[t] = g_part[t];
    __syncthreads();
    for (int o = 512; o; o >>= 1) {
        if (t < o) s[t] = fmaxf(s[t], s[t + o]);
        __syncthreads();
    }
    if (t == 0) g_gmax = s[0];
}

// ---------------- kernel 2: attention over one j-quarter ----------------
// grid 512 = 128 i-tiles x 4 j-quarters. block 128 threads, 64 rows, 32 chunks of 64 j.
// Thread tile: 4 rows (rg=t>>3, rows rg*4..+3) x 8 feats (fg=t&7, feats fg*4..+3 and 32+fg*4..+3).
// p kept ROW-major (no transpose), read as float4 along jj. XOR-swizzled SMEM: conflict-free.
__global__ __launch_bounds__(128, 4) void k_attn(const int* __restrict__ adj) {
    __shared__ float4 h_s4[64 * 16];      // h tile  [jj][f/4], swizzle mask (jj&15)
    __shared__ float4 p_s4[64 * 16];      // p tile  [r][j/4],  swizzle mask ((r>>2)&15)
    __shared__ float  sdL_s[64];          // log2e * s_dst for this chunk
    __shared__ float2 c_s[64];            // per-row: {log2e*ssrc, -log2e*m}
    __shared__ float  zrow_s[64];

    const int t = threadIdx.x;
    const int i_tile = blockIdx.x >> 2;
    const int jq = blockIdx.x & 3;
    const int i0 = i_tile * 64;
    const int jb = jq * 2048;
    const int fg = t & 7;
    const int rg = t >> 3;               // 0..15

    if (t < 64) {
        float ss = g_ssrc[i0 + t];
        float m = lrelu(ss + g_gmax);
        c_s[t] = make_float2(LOG2E * ss, -LOG2E * m);
        zrow_s[t] = 0.f;
    }

    unsigned long long acc[4][4];
#pragma unroll
    for (int i = 0; i < 4; ++i)
#pragma unroll
        for (int k = 0; k < 4; ++k) acc[i][k] = 0ULL;
    float zp[4] = {0.f, 0.f, 0.f, 0.f};

    // prologue: prefetch adj for chunk 0 (4 rows x 2 halves x int4)
    int4 abuf[4][2];
#pragma unroll
    for (int rr = 0; rr < 4; ++rr) {
        const int* ap = adj + (size_t)(i0 + rg * 4 + rr) * Nn + jb;
#pragma unroll
        for (int hh = 0; hh < 2; ++hh)
            abuf[rr][hh] = *(const int4*)(ap + hh * 32 + fg * 4);
    }

    for (int c = 0; c < 32; ++c) {
        const int j0 = c * 64;
        __syncthreads();                  // prev GEMM done with h_s/p_s

        // ---- stage h tile (16KB memcpy with swizzle) ----
        {
            const float4* src = (const float4*)(g_h + (size_t)(jb + j0) * 64);
#pragma unroll
            for (int q = 0; q < 8; ++q) {
                int idx = q * 128 + t;            // 1024 float4
                int jj = idx >> 4, j4 = idx & 15;
                h_s4[jj * 16 + (j4 ^ (jj & 15))] = src[idx];
            }
        }
        if (t < 64) sdL_s[t] = LOG2E * g_sdst[jb + j0 + t];
        __syncthreads();                  // sdL ready (h_s not needed yet by p-phase)

        // ---- compute p tile from prefetched adj ----
#pragma unroll
        for (int rr = 0; rr < 4; ++rr) {
            const int r = rg * 4 + rr;
            const float2 cc = c_s[r];
            float z = 0.f;
#pragma unroll
            for (int hh = 0; hh < 2; ++hh) {
                int4 a = abuf[rr][hh];
                float4 sd = *(const float4*)&sdL_s[(hh * 8 + fg) * 4];
                float4 pv;
                {
                    float u = cc.x + sd.x;
                    float e = exp2f(fmaxf(u + cc.y, fmaf(GAT_ALPHA, u, cc.y)));
                    pv.x = (a.x > 0) ? e : 0.f;
                }
                {
                    float u = cc.x + sd.y;
                    float e = exp2f(fmaxf(u + cc.y, fmaf(GAT_ALPHA, u, cc.y)));
                    pv.y = (a.y > 0) ? e : 0.f;
                }
                {
                    float u = cc.x + sd.z;
                    float e = exp2f(fmaxf(u + cc.y, fmaf(GAT_ALPHA, u, cc.y)));
                    pv.z = (a.z > 0) ? e : 0.f;
                }
                {
                    float u = cc.x + sd.w;
                    float e = exp2f(fmaxf(u + cc.y, fmaf(GAT_ALPHA, u, cc.y)));
                    pv.w = (a.w > 0) ? e : 0.f;
                }
                z += (pv.x + pv.y) + (pv.z + pv.w);
                p_s4[r * 16 + ((hh * 8 + fg) ^ ((r >> 2) & 15))] = pv;
            }
            zp[rr] += z;
        }
        __syncthreads();                  // p_s/h_s ready

        // ---- prefetch adj for next chunk (retires during GEMM) ----
        if (c < 31) {
#pragma unroll
            for (int rr = 0; rr < 4; ++rr) {
                const int* ap = adj + (size_t)(i0 + rg * 4 + rr) * Nn + jb + j0 + 64;
#pragma unroll
                for (int hh = 0; hh < 2; ++hh)
                    abuf[rr][hh] = *(const int4*)(ap + hh * 32 + fg * 4);
            }
        }

        // ---- GEMM: acc[4 rows][8 feats] += p * h ----
#pragma unroll 4
        for (int s = 0; s < 16; ++s) {
            float4 pv[4];
#pragma unroll
            for (int rr = 0; rr < 4; ++rr) {
                const int r = rg * 4 + rr;
                pv[rr] = p_s4[r * 16 + (s ^ ((r >> 2) & 15))];
            }
#pragma unroll
            for (int k = 0; k < 4; ++k) {
                const int jj = s * 4 + k;
                float4 hlo = h_s4[jj * 16 + (fg ^ (jj & 15))];
                float4 hhi = h_s4[jj * 16 + ((8 + fg) ^ (jj & 15))];
                unsigned long long h0 = pack2(hlo.x, hlo.y);
                unsigned long long h1 = pack2(hlo.z, hlo.w);
                unsigned long long h2 = pack2(hhi.x, hhi.y);
                unsigned long long h3 = pack2(hhi.z, hhi.w);
#pragma unroll
                for (int rr = 0; rr < 4; ++rr) {
                    float pk = (k == 0) ? pv[rr].x : (k == 1) ? pv[rr].y
                             : (k == 2) ? pv[rr].z : pv[rr].w;
                    unsigned long long pp = pack2(pk, pk);
                    acc[rr][0] = ffma2(pp, h0, acc[rr][0]);
                    acc[rr][1] = ffma2(pp, h1, acc[rr][1]);
                    acc[rr][2] = ffma2(pp, h2, acc[rr][2]);
                    acc[rr][3] = ffma2(pp, h3, acc[rr][3]);
                }
            }
        }
    }

    // ---- z reduce + write partials ----
    __syncthreads();
#pragma unroll
    for (int rr = 0; rr < 4; ++rr)
        atomicAdd(&zrow_s[rg * 4 + rr], zp[rr]);

    float* ob = g_o4 + (size_t)jq * Nn * 64;
#pragma unroll
    for (int rr = 0; rr < 4; ++rr) {
        const int r = rg * 4 + rr;
        float2 a0 = unpack2(acc[rr][0]);
        float2 a1 = unpack2(acc[rr][1]);
        float2 a2 = unpack2(acc[rr][2]);
        float2 a3 = unpack2(acc[rr][3]);
        float4 lo = make_float4(a0.x, a0.y, a1.x, a1.y);
        float4 hi = make_float4(a2.x, a2.y, a3.x, a3.y);
        *(float4*)(ob + (size_t)(i0 + r) * 64 + fg * 4) = lo;
        *(float4*)(ob + (size_t)(i0 + r) * 64 + 32 + fg * 4) = hi;
    }
    __syncthreads();
    if (t < 64) g_z4[jq * Nn + i0 + t] = zrow_s[t];
}

// ---------------- kernel 3: combine quarters + normalize ----------------
__global__ __launch_bounds__(256) void k_norm(float* __restrict__ out) {
    const int idx = blockIdx.x * 256 + threadIdx.x;     // float4 index, 131072 total
    const int row = idx >> 4;
    const float4* o0 = (const float4*)g_o4;
    float4 a = o0[idx];
    float4 b = o0[idx + Nn * 16];
    float4 c = o0[idx + 2 * Nn * 16];
    float4 d = o0[idx + 3 * Nn * 16];
    float z = g_z4[row] + g_z4[Nn + row] + g_z4[2 * Nn + row] + g_z4[3 * Nn + row];
    float zi = 1.0f / z;
    float4 o;
    o.x = (a.x + b.x + c.x + d.x) * zi;
    o.y = (a.y + b.y + c.y + d.y) * zi;
    o.z = (a.z + b.z + c.z + d.z) * zi;
    o.w = (a.w + b.w + c.w + d.w) * zi;
    ((float4*)out)[idx] = o;
}

// ---------------- launch ----------------
extern "C" void kernel_launch(void* const* d_in, const int* in_sizes, int n_in,
                              void* d_out, int out_size) {
    const float* input = (const float*)d_in[0];
    const int*   adj   = (const int*)d_in[1];
    const float* Wm    = (const float*)d_in[2];
    const float* av    = (const float*)d_in[3];
    float* out = (float*)d_out;

    k_proj<<<Nn / 16, 256>>>(input, Wm);
    k_scores<<<Nn / 8, 256>>>(av);
    k_max<<<1, 1024>>>();
    k_attn<<<512, 128>>>(adj);
    k_norm<<<512, 256>>>(out);
}